// round 16
// baseline (speedup 1.0000x reference)
#include <cuda_runtime.h>
#include <cuda_fp16.h>

#define NN 100000
#define EE 1600000
#define FH 32
#define SCAN_BLOCKS 98               // 98*1024 = 100352 >= NN
typedef unsigned long long ULL;

// ---------------- device scratch (static; no allocations) ----------------
// zero-init contract: g_deg and g_cnt are zero at module load (BSS) and are
// re-zeroed by the pipeline itself each call (g_cnt in scan3; g_deg in agg_xh).
__device__ __align__(16) int    g_src[EE];
__device__ __align__(16) int    g_dst[EE];
__device__ __align__(16) ULL    g_edges[EE];      // CSR by dst: {src lo32, nw bits hi32}
__device__ __align__(16) float  g_deg[NN];        // weighted out-degree, then dinv
__device__ __align__(16) int    g_cnt[NN];        // in-degree histogram
__device__ __align__(16) int    g_off[NN + 1];    // CSR offsets
__device__ __align__(16) int    g_cursor[NN];
__device__ __align__(16) int    g_blocksum[128];  // padded to 128
__device__ __align__(16) __half g_xh16[NN * 64];  // per node: q-th 8: x[q*4..+4) then H[q*4..+4)
__device__ __align__(16) __half g_hr16[NN * FH];  // fp16 H*R (gather source AND out-GEMM input)
__device__ __align__(16) float  g_aggx[NN * FH];
__device__ __align__(16) float  g_aggh[NN * FH];
__device__ __align__(16) float  g_agghr[NN * FH];
__device__ __align__(16) float  g_Z[NN * FH];

// packed fp32x2 helpers (exact fp32 lanewise)
__device__ __forceinline__ ULL fma2(ULL a, ULL b, ULL c) {
    ULL d;
    asm("fma.rn.f32x2 %0, %1, %2, %3;" : "=l"(d) : "l"(a), "l"(b), "l"(c));
    return d;
}
__device__ __forceinline__ ULL dup2(float w) {
    ULL d; unsigned u = __float_as_uint(w);
    asm("mov.b64 %0, {%1, %2};" : "=l"(d) : "r"(u), "r"(u));
    return d;
}
__device__ __forceinline__ float lo2(ULL v) { return __uint_as_float((unsigned)v); }
__device__ __forceinline__ float hi2(ULL v) { return __uint_as_float((unsigned)(v >> 32)); }

// ---------------- kernels ----------------

// Fused: dtype probe + fp16 pack of x/H + index convert (4 edges/thread,
// batched loads for MLP) + weighted out-degree + in-degree histogram.
__global__ void packA_kernel(const void* ei, const float* __restrict__ x,
                             const float* __restrict__ H,
                             const float* __restrict__ ew) {
    __shared__ int s_is64;
    if (threadIdx.x == 0) {
        const ULL* p = (const ULL*)ei;
        int is64 = 1;
        for (int k = 0; k < 16; k++)
            if (p[k] >= (ULL)NN) is64 = 0;
        s_is64 = is64;
    }
    __syncthreads();
    int i = blockIdx.x * blockDim.x + threadIdx.x;

    if (i < NN * 8) {                 // i = node*8 + q
        int off = i * 4;
        float4 xv = *(const float4*)(x + off);
        float4 hv = *(const float4*)(H + off);
        __half* dst = g_xh16 + (size_t)i * 8;
        *(__half2*)(dst)     = __floats2half2_rn(xv.x, xv.y);
        *(__half2*)(dst + 2) = __floats2half2_rn(xv.z, xv.w);
        *(__half2*)(dst + 4) = __floats2half2_rn(hv.x, hv.y);
        *(__half2*)(dst + 6) = __floats2half2_rn(hv.z, hv.w);
    }

    int e0 = i * 4;
    if (e0 < EE) {
        int s[4], d[4];
        if (s_is64) {
            longlong4 sv = *(const longlong4*)((const long long*)ei + e0);
            longlong4 dv = *(const longlong4*)((const long long*)ei + EE + e0);
            s[0] = (int)sv.x; s[1] = (int)sv.y; s[2] = (int)sv.z; s[3] = (int)sv.w;
            d[0] = (int)dv.x; d[1] = (int)dv.y; d[2] = (int)dv.z; d[3] = (int)dv.w;
        } else {
            int4 sv = *(const int4*)((const int*)ei + e0);
            int4 dv = *(const int4*)((const int*)ei + EE + e0);
            s[0] = sv.x; s[1] = sv.y; s[2] = sv.z; s[3] = sv.w;
            d[0] = dv.x; d[1] = dv.y; d[2] = dv.z; d[3] = dv.w;
        }
        float4 w4 = *(const float4*)(ew + e0);
        float wv[4] = {w4.x, w4.y, w4.z, w4.w};
        *(int4*)(g_src + e0) = make_int4(s[0], s[1], s[2], s[3]);
        *(int4*)(g_dst + e0) = make_int4(d[0], d[1], d[2], d[3]);
#pragma unroll
        for (int k = 0; k < 4; k++) {
            float w = (s[k] == d[k]) ? 0.f : wv[k];
            if (w != 0.f) atomicAdd(&g_deg[s[k]], w);
            atomicAdd(&g_cnt[d[k]], 1);
        }
    }
}

// scan phase 1 (block sums of cnt) + fused dinv (independent elementwise).
__global__ void __launch_bounds__(1024) scan1_kernel() {
    int i = blockIdx.x * 1024 + threadIdx.x;
    if (i < NN) {
        float dg = g_deg[i];
        g_deg[i] = (dg > 0.f) ? rsqrtf(fmaxf(dg, 1e-30f)) : 0.f;
    }
    int v = (i < NN) ? g_cnt[i] : 0;
#pragma unroll
    for (int off = 16; off; off >>= 1) v += __shfl_xor_sync(0xffffffffu, v, off);
    __shared__ int ws[32];
    if ((threadIdx.x & 31) == 0) ws[threadIdx.x >> 5] = v;
    __syncthreads();
    if (threadIdx.x < 32) {
        int s = ws[threadIdx.x];
#pragma unroll
        for (int off = 16; off; off >>= 1) s += __shfl_xor_sync(0xffffffffu, s, off);
        if (threadIdx.x == 0) g_blocksum[blockIdx.x] = s;
    }
}

// scan phase 2: redundant block-sum scan + intra-block scan -> g_off/g_cursor.
// Also re-zeroes g_cnt for the next kernel_launch call.
__global__ void __launch_bounds__(1024) scan3_kernel() {
    int t = threadIdx.x;
    int i = blockIdx.x * 1024 + t;
    int lane = t & 31, wid = t >> 5;

    __shared__ int pre[128];
    if (t < 128) pre[t] = (t < SCAN_BLOCKS) ? g_blocksum[t] : 0;
    __syncthreads();
    for (int off = 1; off < 128; off <<= 1) {
        int v = 0;
        if (t < 128 && t >= off) v = pre[t - off];
        __syncthreads();
        if (t < 128) pre[t] += v;
        __syncthreads();
    }
    int blockpre = (blockIdx.x == 0) ? 0 : pre[blockIdx.x - 1];

    int v = (i < NN) ? g_cnt[i] : 0;
    int sv = v;
#pragma unroll
    for (int off = 1; off < 32; off <<= 1) {
        int n = __shfl_up_sync(0xffffffffu, sv, off);
        if (lane >= off) sv += n;
    }
    __shared__ int ws[32];
    if (lane == 31) ws[wid] = sv;
    __syncthreads();
    if (t < 32) {
        int s = ws[t];
#pragma unroll
        for (int off = 1; off < 32; off <<= 1) {
            int n = __shfl_up_sync(0xffffffffu, s, off);
            if (t >= off) s += n;
        }
        ws[t] = s;
    }
    __syncthreads();
    int warpbase = (wid == 0) ? 0 : ws[wid - 1];
    int excl = blockpre + warpbase + sv - v;
    if (i < NN) {
        g_off[i] = excl;
        g_cursor[i] = excl;
        g_cnt[i] = 0;                  // deferred cleanup for next call
        if (i == NN - 1) g_off[NN] = excl + v;
    }
}

// bucket-scatter packed edge records {src, nw} — 4 edges/thread, batched.
__global__ void passB_kernel(const float* __restrict__ ew) {
    int e0 = (blockIdx.x * blockDim.x + threadIdx.x) * 4;
    if (e0 >= EE) return;
    int4 s4 = *(const int4*)(g_src + e0);
    int4 d4 = *(const int4*)(g_dst + e0);
    float4 w4 = *(const float4*)(ew + e0);
    int s[4] = {s4.x, s4.y, s4.z, s4.w};
    int d[4] = {d4.x, d4.y, d4.z, d4.w};
    float wv[4] = {w4.x, w4.y, w4.z, w4.w};
    // front-batch all deg loads (8 independent)
    float ds[4], dd[4];
#pragma unroll
    for (int k = 0; k < 4; k++) { ds[k] = g_deg[s[k]]; dd[k] = g_deg[d[k]]; }
    float nw[4];
#pragma unroll
    for (int k = 0; k < 4; k++) {
        float w = (s[k] == d[k]) ? 0.f : wv[k];
        nw[k] = w * ds[k] * dd[k];
    }
    // batch atomics (independent; overlap their latency)
    int pos[4];
#pragma unroll
    for (int k = 0; k < 4; k++) pos[k] = atomicAdd(&g_cursor[d[k]], 1);
#pragma unroll
    for (int k = 0; k < 4; k++)
        g_edges[pos[k]] = (unsigned)s[k] | ((ULL)__float_as_uint(nw[k]) << 32);
}

// Gather-aggregate x and H per dst node. Warp per node: 4 edge-slots x 8 threads.
// Also re-zeroes g_deg (passB was the last reader) for the next call.
__global__ void __launch_bounds__(256) agg_xh_kernel() {
    int gi = blockIdx.x * 256 + threadIdx.x;
    if (gi < NN) g_deg[gi] = 0.f;      // deferred cleanup for next call
    int node = gi >> 5;
    if (node >= NN) return;
    int lane = threadIdx.x & 31;
    int slot = lane >> 3;
    int q = lane & 7;
    int beg = g_off[node];
    int deg = g_off[node + 1] - beg;

    float ax0 = 0.f, ax1 = 0.f, ax2 = 0.f, ax3 = 0.f;
    float ah0 = 0.f, ah1 = 0.f, ah2 = 0.f, ah3 = 0.f;
    int j = slot;
    for (; j + 4 < deg; j += 8) {
        ULL r0 = g_edges[beg + j];
        ULL r1 = g_edges[beg + j + 4];
        int s0 = (int)(unsigned)r0, s1 = (int)(unsigned)r1;
        float w0 = __uint_as_float((unsigned)(r0 >> 32));
        float w1 = __uint_as_float((unsigned)(r1 >> 32));
        uint4 p0 = *(const uint4*)(g_xh16 + (size_t)s0 * 64 + q * 8);
        uint4 p1 = *(const uint4*)(g_xh16 + (size_t)s1 * 64 + q * 8);
        {
            float2 a = __half22float2(*(__half2*)&p0.x);
            float2 b = __half22float2(*(__half2*)&p0.y);
            float2 c = __half22float2(*(__half2*)&p0.z);
            float2 d = __half22float2(*(__half2*)&p0.w);
            ax0 = fmaf(w0, a.x, ax0); ax1 = fmaf(w0, a.y, ax1);
            ax2 = fmaf(w0, b.x, ax2); ax3 = fmaf(w0, b.y, ax3);
            ah0 = fmaf(w0, c.x, ah0); ah1 = fmaf(w0, c.y, ah1);
            ah2 = fmaf(w0, d.x, ah2); ah3 = fmaf(w0, d.y, ah3);
        }
        {
            float2 a = __half22float2(*(__half2*)&p1.x);
            float2 b = __half22float2(*(__half2*)&p1.y);
            float2 c = __half22float2(*(__half2*)&p1.z);
            float2 d = __half22float2(*(__half2*)&p1.w);
            ax0 = fmaf(w1, a.x, ax0); ax1 = fmaf(w1, a.y, ax1);
            ax2 = fmaf(w1, b.x, ax2); ax3 = fmaf(w1, b.y, ax3);
            ah0 = fmaf(w1, c.x, ah0); ah1 = fmaf(w1, c.y, ah1);
            ah2 = fmaf(w1, d.x, ah2); ah3 = fmaf(w1, d.y, ah3);
        }
    }
    if (j < deg) {
        ULL r0 = g_edges[beg + j];
        int s0 = (int)(unsigned)r0;
        float w0 = __uint_as_float((unsigned)(r0 >> 32));
        uint4 p0 = *(const uint4*)(g_xh16 + (size_t)s0 * 64 + q * 8);
        float2 a = __half22float2(*(__half2*)&p0.x);
        float2 b = __half22float2(*(__half2*)&p0.y);
        float2 c = __half22float2(*(__half2*)&p0.z);
        float2 d = __half22float2(*(__half2*)&p0.w);
        ax0 = fmaf(w0, a.x, ax0); ax1 = fmaf(w0, a.y, ax1);
        ax2 = fmaf(w0, b.x, ax2); ax3 = fmaf(w0, b.y, ax3);
        ah0 = fmaf(w0, c.x, ah0); ah1 = fmaf(w0, c.y, ah1);
        ah2 = fmaf(w0, d.x, ah2); ah3 = fmaf(w0, d.y, ah3);
    }
#pragma unroll
    for (int off = 8; off <= 16; off <<= 1) {
        ax0 += __shfl_xor_sync(0xffffffffu, ax0, off);
        ax1 += __shfl_xor_sync(0xffffffffu, ax1, off);
        ax2 += __shfl_xor_sync(0xffffffffu, ax2, off);
        ax3 += __shfl_xor_sync(0xffffffffu, ax3, off);
        ah0 += __shfl_xor_sync(0xffffffffu, ah0, off);
        ah1 += __shfl_xor_sync(0xffffffffu, ah1, off);
        ah2 += __shfl_xor_sync(0xffffffffu, ah2, off);
        ah3 += __shfl_xor_sync(0xffffffffu, ah3, off);
    }
    if (slot == 0) {
        *(float4*)(g_aggx + (size_t)node * FH + q * 4) = make_float4(ax0, ax1, ax2, ax3);
        *(float4*)(g_aggh + (size_t)node * FH + q * 4) = make_float4(ah0, ah1, ah2, ah3);
    }
}

// Gather-aggregate H*R per dst node (fp16 source), pipelined the same way.
__global__ void __launch_bounds__(256) agg_hr_kernel() {
    int node = (blockIdx.x * 256 + threadIdx.x) >> 5;
    if (node >= NN) return;
    int lane = threadIdx.x & 31;
    int slot = lane >> 3;
    int q = lane & 7;
    int beg = g_off[node];
    int deg = g_off[node + 1] - beg;

    float a0 = 0.f, a1 = 0.f, a2 = 0.f, a3 = 0.f;
    int j = slot;
    for (; j + 4 < deg; j += 8) {
        ULL r0 = g_edges[beg + j];
        ULL r1 = g_edges[beg + j + 4];
        int s0 = (int)(unsigned)r0, s1 = (int)(unsigned)r1;
        float w0 = __uint_as_float((unsigned)(r0 >> 32));
        float w1 = __uint_as_float((unsigned)(r1 >> 32));
        uint2 p0 = *(const uint2*)(g_hr16 + (size_t)s0 * FH + q * 4);
        uint2 p1 = *(const uint2*)(g_hr16 + (size_t)s1 * FH + q * 4);
        {
            float2 a = __half22float2(*(__half2*)&p0.x);
            float2 b = __half22float2(*(__half2*)&p0.y);
            a0 = fmaf(w0, a.x, a0); a1 = fmaf(w0, a.y, a1);
            a2 = fmaf(w0, b.x, a2); a3 = fmaf(w0, b.y, a3);
        }
        {
            float2 a = __half22float2(*(__half2*)&p1.x);
            float2 b = __half22float2(*(__half2*)&p1.y);
            a0 = fmaf(w1, a.x, a0); a1 = fmaf(w1, a.y, a1);
            a2 = fmaf(w1, b.x, a2); a3 = fmaf(w1, b.y, a3);
        }
    }
    if (j < deg) {
        ULL r0 = g_edges[beg + j];
        int s0 = (int)(unsigned)r0;
        float w0 = __uint_as_float((unsigned)(r0 >> 32));
        uint2 p0 = *(const uint2*)(g_hr16 + (size_t)s0 * FH + q * 4);
        float2 a = __half22float2(*(__half2*)&p0.x);
        float2 b = __half22float2(*(__half2*)&p0.y);
        a0 = fmaf(w0, a.x, a0); a1 = fmaf(w0, a.y, a1);
        a2 = fmaf(w0, b.x, a2); a3 = fmaf(w0, b.y, a3);
    }
#pragma unroll
    for (int off = 8; off <= 16; off <<= 1) {
        a0 += __shfl_xor_sync(0xffffffffu, a0, off);
        a1 += __shfl_xor_sync(0xffffffffu, a1, off);
        a2 += __shfl_xor_sync(0xffffffffu, a2, off);
        a3 += __shfl_xor_sync(0xffffffffu, a3, off);
    }
    if (slot == 0)
        *(float4*)(g_agghr + (size_t)node * FH + q * 4) = make_float4(a0, a1, a2, a3);
}

// ---------------- gate GEMM: 8 nodes per warp, f32x2 ----------------
// dyn smem floats: sW[8192] | sInF[32*260] | sbz[32] | sbr[32]
#define GATE_SMEM_FLOATS (8192 + 32 * 260 + 64)
__global__ void __launch_bounds__(256) gate_kernel(
    const float* __restrict__ x, const float* __restrict__ H,
    const float* __restrict__ Wxz, const float* __restrict__ bxz,
    const float* __restrict__ Whz, const float* __restrict__ bhz,
    const float* __restrict__ Wxr, const float* __restrict__ bxr,
    const float* __restrict__ Whr, const float* __restrict__ bhr) {
    extern __shared__ __align__(16) float dyn[];
    float* sW   = dyn;                 // [Wxz0,-Wxz1, Whz0,-Whz1, Wxr0,-Wxr1, Whr0,-Whr1]
    float* sInF = dyn + 8192;          // [k][array(4)*64 + node(64)], row = 260 floats
    float* sbz  = dyn + 8192 + 32 * 260;
    float* sbr  = sbz + 32;

    const float* mats[4] = {Wxz, Whz, Wxr, Whr};
    for (int i = threadIdx.x; i < 8 * 1024; i += blockDim.x) {
        int m = i >> 10;
        int r = i & 1023;
        float v = mats[m >> 1][(m & 1) * 1024 + r];
        sW[i] = (m & 1) ? -v : v;
    }
    if (threadIdx.x < 32) {
        sbz[threadIdx.x] = bxz[threadIdx.x] + bhz[threadIdx.x];
        sbr[threadIdx.x] = bxr[threadIdx.x] + bhr[threadIdx.x];
    }
    __syncthreads();

    int w = threadIdx.x >> 5;
    int lane = threadIdx.x & 31;
    int nbase = blockIdx.x * 64 + w * 8;

#pragma unroll
    for (int i = 0; i < 8; i++) {
        int cn = min(nbase + i, NN - 1);
        size_t b = (size_t)cn * FH + lane;
        int off = lane * 260 + w * 8 + i;
        sInF[off]       = x[b];
        sInF[off + 64]  = g_aggx[b];
        sInF[off + 128] = H[b];
        sInF[off + 192] = g_aggh[b];
    }
    __syncwarp();

    ULL az[4], ar[4];
    ULL bz0 = dup2(sbz[lane]), br0 = dup2(sbr[lane]);
#pragma unroll
    for (int j = 0; j < 4; j++) { az[j] = bz0; ar[j] = br0; }
    int pb = w * 4;

#pragma unroll
    for (int k = 0; k < 32; k++) {
        const float* wrow = sW + k * 32 + lane;
        ULL w0 = dup2(wrow[0]);
        ULL w1 = dup2(wrow[1024]);
        ULL w2 = dup2(wrow[2048]);
        ULL w3 = dup2(wrow[3072]);
        ULL w4 = dup2(wrow[4096]);
        ULL w5 = dup2(wrow[5120]);
        ULL w6 = dup2(wrow[6144]);
        ULL w7 = dup2(wrow[7168]);
        const ULL* inrow = (const ULL*)(sInF + k * 260);
#pragma unroll
        for (int j = 0; j < 4; j++) {
            ULL xv = inrow[pb + j];
            ULL av = inrow[32 + pb + j];
            ULL hv = inrow[64 + pb + j];
            ULL gv = inrow[96 + pb + j];
            az[j] = fma2(xv, w0, az[j]); az[j] = fma2(av, w1, az[j]);
            az[j] = fma2(hv, w2, az[j]); az[j] = fma2(gv, w3, az[j]);
            ar[j] = fma2(xv, w4, ar[j]); ar[j] = fma2(av, w5, ar[j]);
            ar[j] = fma2(hv, w6, ar[j]); ar[j] = fma2(gv, w7, ar[j]);
        }
    }

#pragma unroll
    for (int i = 0; i < 8; i++) {
        int node = nbase + i;
        if (node >= NN) break;
        int j = i >> 1;
        float zp = (i & 1) ? hi2(az[j]) : lo2(az[j]);
        float rp = (i & 1) ? hi2(ar[j]) : lo2(ar[j]);
        size_t b = (size_t)node * FH + lane;
        float z = 1.f / (1.f + __expf(-zp));
        float r = 1.f / (1.f + __expf(-rp));
        float hv = sInF[lane * 260 + 128 + w * 8 + i];
        float hr = hv * r;
        g_Z[b]    = z;
        g_hr16[b] = __float2half_rn(hr);   // single HR representation (fp16)
    }
}

// ---------------- out GEMM: 8 nodes per warp, f32x2 ----------------
// dyn smem floats: sW[4096] | sInF[32*260] | sbh[32] | slw[128] | slb[4]
#define OUT_SMEM_FLOATS (4096 + 32 * 260 + 32 + 128 + 4)
__global__ void __launch_bounds__(256) out_kernel(
    const float* __restrict__ x, const float* __restrict__ H,
    const float* __restrict__ Wxh, const float* __restrict__ bxh,
    const float* __restrict__ Whh, const float* __restrict__ bhh,
    const float* __restrict__ lw, const float* __restrict__ lb,
    float* __restrict__ out, int out_size) {
    extern __shared__ __align__(16) float dyn[];
    float* sW   = dyn;                 // [Wxh0, -Wxh1, Whh0, -Whh1]
    float* sInF = dyn + 4096;
    float* sbh  = dyn + 4096 + 32 * 260;
    float* slw  = sbh + 32;
    float* slb  = slw + 128;

    for (int i = threadIdx.x; i < 4 * 1024; i += blockDim.x) {
        int m = i >> 10;
        int r = i & 1023;
        const float* Wp = (m < 2) ? Wxh : Whh;
        float v = Wp[(m & 1) * 1024 + r];
        sW[i] = (m & 1) ? -v : v;
    }
    if (threadIdx.x < 32) sbh[threadIdx.x] = bxh[threadIdx.x] + bhh[threadIdx.x];
    if (threadIdx.x < 128) slw[threadIdx.x] = lw[threadIdx.x];
    if (threadIdx.x < 4) slb[threadIdx.x] = lb[threadIdx.x];
    __syncthreads();

    int w = threadIdx.x >> 5;
    int lane = threadIdx.x & 31;
    int nbase = blockIdx.x * 64 + w * 8;

#pragma unroll
    for (int i = 0; i < 8; i++) {
        int cn = min(nbase + i, NN - 1);
        size_t b = (size_t)cn * FH + lane;
        int off = lane * 260 + w * 8 + i;
        sInF[off]       = x[b];
        sInF[off + 64]  = g_aggx[b];
        sInF[off + 128] = __half2float(g_hr16[b]);   // HR from fp16 (no fp32 round-trip)
        sInF[off + 192] = g_agghr[b];
    }
    __syncwarp();

    ULL acc[4];
    ULL b0 = dup2(sbh[lane]);
#pragma unroll
    for (int j = 0; j < 4; j++) acc[j] = b0;
    int pb = w * 4;

#pragma unroll
    for (int k = 0; k < 32; k++) {
        const float* wrow = sW + k * 32 + lane;
        ULL w0 = dup2(wrow[0]);
        ULL w1 = dup2(wrow[1024]);
        ULL w2 = dup2(wrow[2048]);
        ULL w3 = dup2(wrow[3072]);
        const ULL* inrow = (const ULL*)(sInF + k * 260);
#pragma unroll
        for (int j = 0; j < 4; j++) {
            ULL xv = inrow[pb + j];
            ULL av = inrow[32 + pb + j];
            ULL hv = inrow[64 + pb + j];
            ULL gv = inrow[96 + pb + j];
            acc[j] = fma2(xv, w0, acc[j]); acc[j] = fma2(av, w1, acc[j]);
            acc[j] = fma2(hv, w2, acc[j]); acc[j] = fma2(gv, w3, acc[j]);
        }
    }

#pragma unroll
    for (int i = 0; i < 8; i++) {
        int node = nbase + i;
        if (node >= NN) break;
        int j = i >> 1;
        float ap = (i & 1) ? hi2(acc[j]) : lo2(acc[j]);
        size_t b = (size_t)node * FH + lane;
        float ht = tanhf(ap);
        float z = g_Z[b];
        float hval = z * H[b] + (1.f - z) * ht;

        long long hidx = (long long)NN * 4 + (long long)b;
        if (hidx < (long long)out_size) out[hidx] = hval;

        float rh = fmaxf(hval, 0.f);
#pragma unroll
        for (int jj = 0; jj < 4; jj++) {
            float s = rh * slw[lane * 4 + jj];
#pragma unroll
            for (int off = 16; off; off >>= 1) s += __shfl_xor_sync(0xffffffffu, s, off);
            if (lane == 0 && (long long)node * 4 + jj < (long long)out_size)
                out[(size_t)node * 4 + jj] = s + slb[jj];
        }
    }
}

// ---------------- launch ----------------
extern "C" void kernel_launch(void* const* d_in, const int* in_sizes, int n_in,
                              void* d_out, int out_size) {
    const float* x   = (const float*)d_in[0];
    const void*  ei  = d_in[1];
    const float* ew  = (const float*)d_in[2];
    const float* H   = (const float*)d_in[3];
    const float* Wxz = (const float*)d_in[4];
    const float* bxz = (const float*)d_in[5];
    const float* Whz = (const float*)d_in[6];
    const float* bhz = (const float*)d_in[7];
    const float* Wxr = (const float*)d_in[8];
    const float* bxr = (const float*)d_in[9];
    const float* Whr = (const float*)d_in[10];
    const float* bhr = (const float*)d_in[11];
    const float* Wxh = (const float*)d_in[12];
    const float* bxh = (const float*)d_in[13];
    const float* Whh = (const float*)d_in[14];
    const float* bhh = (const float*)d_in[15];
    const float* lw  = (const float*)d_in[16];
    const float* lb  = (const float*)d_in[17];
    float* out = (float*)d_out;

    static int smem_set = 0;
    if (!smem_set) {
        cudaFuncSetAttribute(gate_kernel, cudaFuncAttributeMaxDynamicSharedMemorySize,
                             GATE_SMEM_FLOATS * 4);
        cudaFuncSetAttribute(out_kernel, cudaFuncAttributeMaxDynamicSharedMemorySize,
                             OUT_SMEM_FLOATS * 4);
        smem_set = 1;
    }

    // grid sized for max(NN*8 pack items, EE/4 edge groups) = NN*8
    packA_kernel<<<(NN * 8 + 255) / 256, 256>>>(ei, x, H, ew);
    scan1_kernel<<<SCAN_BLOCKS, 1024>>>();
    scan3_kernel<<<SCAN_BLOCKS, 1024>>>();
    passB_kernel<<<(EE / 4 + 255) / 256, 256>>>(ew);
    agg_xh_kernel<<<(NN + 7) / 8, 256>>>();
    gate_kernel<<<(NN + 63) / 64, 256, GATE_SMEM_FLOATS * 4>>>(
        x, H, Wxz, bxz, Whz, bhz, Wxr, bxr, Whr, bhr);
    agg_hr_kernel<<<(NN + 7) / 8, 256>>>();
    out_kernel<<<(NN + 63) / 64, 256, OUT_SMEM_FLOATS * 4>>>(
        x, H, Wxh, bxh, Whh, bhh, lw, lb, out, out_size);
}

// round 17
// speedup vs baseline: 1.0302x; 1.0302x over previous
#include <cuda_runtime.h>
#include <cuda_fp16.h>

#define NN 100000
#define EE 1600000
#define FH 32
#define SCAN_BLOCKS 98               // 98*1024 = 100352 >= NN; 98 < 148 SMs (co-resident)
typedef unsigned long long ULL;

// ---------------- device scratch (static; no allocations) ----------------
// zero-init contract: g_deg, g_cnt, g_scanflag are zero at module load (BSS)
// and re-zeroed by the pipeline each call (g_cnt in scan; g_deg+flags in out).
__device__ __align__(16) int    g_src[EE];
__device__ __align__(16) int    g_dst[EE];
__device__ __align__(16) ULL    g_edges[EE];      // CSR by dst: {src lo32, rw=w*dinv[src] hi32}
__device__ __align__(16) float  g_deg[NN];        // weighted out-degree, then dinv (kept until out)
__device__ __align__(16) int    g_cnt[NN];        // in-degree histogram
__device__ __align__(16) int    g_off[NN + 1];    // CSR offsets
__device__ __align__(16) int    g_cursor[NN];
__device__ __align__(16) int    g_scanflag[SCAN_BLOCKS];
__device__ __align__(16) int    g_scanagg[SCAN_BLOCKS];
__device__ __align__(16) __half g_xh16[NN * 64];  // per node: q-th 8: x[q*4..+4) then H[q*4..+4)
__device__ __align__(16) __half g_hr16[NN * FH];  // fp16 H*R (gather source AND out-GEMM input)
__device__ __align__(16) float  g_aggx[NN * FH];
__device__ __align__(16) float  g_aggh[NN * FH];
__device__ __align__(16) float  g_agghr[NN * FH];
__device__ __align__(16) float  g_Z[NN * FH];

// packed fp32x2 helpers (exact fp32 lanewise)
__device__ __forceinline__ ULL fma2(ULL a, ULL b, ULL c) {
    ULL d;
    asm("fma.rn.f32x2 %0, %1, %2, %3;" : "=l"(d) : "l"(a), "l"(b), "l"(c));
    return d;
}
__device__ __forceinline__ ULL dup2(float w) {
    ULL d; unsigned u = __float_as_uint(w);
    asm("mov.b64 %0, {%1, %2};" : "=l"(d) : "r"(u), "r"(u));
    return d;
}
__device__ __forceinline__ float lo2(ULL v) { return __uint_as_float((unsigned)v); }
__device__ __forceinline__ float hi2(ULL v) { return __uint_as_float((unsigned)(v >> 32)); }

// ---------------- kernels ----------------

// Fused: dtype probe + fp16 pack of x/H + index convert + degree/histogram.
__global__ void packA_kernel(const void* ei, const float* __restrict__ x,
                             const float* __restrict__ H,
                             const float* __restrict__ ew) {
    __shared__ int s_is64;
    if (threadIdx.x == 0) {
        const ULL* p = (const ULL*)ei;
        int is64 = 1;
        for (int k = 0; k < 16; k++)
            if (p[k] >= (ULL)NN) is64 = 0;
        s_is64 = is64;
    }
    __syncthreads();
    int i = blockIdx.x * blockDim.x + threadIdx.x;

    if (i < NN * 8) {                 // i = node*8 + q
        int off = i * 4;
        float4 xv = *(const float4*)(x + off);
        float4 hv = *(const float4*)(H + off);
        __half* dst = g_xh16 + (size_t)i * 8;
        *(__half2*)(dst)     = __floats2half2_rn(xv.x, xv.y);
        *(__half2*)(dst + 2) = __floats2half2_rn(xv.z, xv.w);
        *(__half2*)(dst + 4) = __floats2half2_rn(hv.x, hv.y);
        *(__half2*)(dst + 6) = __floats2half2_rn(hv.z, hv.w);
    }
    if (i < EE) {
        int s, d;
        if (s_is64) {
            const long long* p = (const long long*)ei;
            s = (int)p[i]; d = (int)p[EE + i];
        } else {
            const int* p = (const int*)ei;
            s = p[i]; d = p[EE + i];
        }
        g_src[i] = s;
        g_dst[i] = d;
        float w = (s == d) ? 0.f : ew[i];
        if (w != 0.f) atomicAdd(&g_deg[s], w);
        atomicAdd(&g_cnt[d], 1);
    }
}

// Single-kernel cooperative scan: dinv + block sums + flag-publish +
// all-blocks redundant scan of the 98 aggregates -> g_off/g_cursor.
// Also re-zeroes g_cnt. Deadlock-free: 98 blocks < 148 SMs, all resident.
__global__ void __launch_bounds__(1024) scan_kernel() {
    int t = threadIdx.x;
    int bid = blockIdx.x;
    int i = bid * 1024 + t;
    int lane = t & 31, wid = t >> 5;

    if (i < NN) {
        float dg = g_deg[i];
        g_deg[i] = (dg > 0.f) ? rsqrtf(fmaxf(dg, 1e-30f)) : 0.f;
    }

    int v = (i < NN) ? g_cnt[i] : 0;
    int sv = v;
#pragma unroll
    for (int off = 1; off < 32; off <<= 1) {
        int n = __shfl_up_sync(0xffffffffu, sv, off);
        if (lane >= off) sv += n;
    }
    __shared__ int ws[32];
    if (lane == 31) ws[wid] = sv;
    __syncthreads();
    if (t < 32) {
        int s = ws[t];
#pragma unroll
        for (int off = 1; off < 32; off <<= 1) {
            int n = __shfl_up_sync(0xffffffffu, s, off);
            if (t >= off) s += n;
        }
        ws[t] = s;
    }
    __syncthreads();
    int warpbase = (wid == 0) ? 0 : ws[wid - 1];

    // publish this block's total
    if (t == 0) {
        g_scanagg[bid] = ws[31];
        __threadfence();
        atomicExch(&g_scanflag[bid], 1);
    }

    // wait for all blocks' totals, scan them (redundantly per block)
    __shared__ int pre[128];
    if (t < 128) pre[t] = 0;
    __syncthreads();
    if (t < SCAN_BLOCKS) {
        while (atomicAdd(&g_scanflag[t], 0) == 0) {}
        pre[t] = g_scanagg[t];
    }
    __syncthreads();
    for (int off = 1; off < 128; off <<= 1) {
        int pv = 0;
        if (t < 128 && t >= off) pv = pre[t - off];
        __syncthreads();
        if (t < 128) pre[t] += pv;
        __syncthreads();
    }
    int blockpre = (bid == 0) ? 0 : pre[bid - 1];

    int excl = blockpre + warpbase + sv - v;
    if (i < NN) {
        g_off[i] = excl;
        g_cursor[i] = excl;
        g_cnt[i] = 0;                  // deferred cleanup for next call
        if (i == NN - 1) g_off[NN] = excl + v;
    }
}

// bucket-scatter packed edge records {src, rw=w*dinv[src]} (one random load).
__global__ void passB_kernel(const float* __restrict__ ew) {
    int e = blockIdx.x * blockDim.x + threadIdx.x;
    if (e >= EE) return;
    int s = g_src[e];
    int d = g_dst[e];
    float w = (s == d) ? 0.f : ew[e];
    float rw = w * g_deg[s];           // dinv[dst] applied later per-node
    int pos = atomicAdd(&g_cursor[d], 1);
    g_edges[pos] = (unsigned)s | ((ULL)__float_as_uint(rw) << 32);
}

// Gather-aggregate x and H per dst node. Warp per node: 4 edge-slots x 8 threads.
// Final per-node scale by dinv[node] (replaces per-edge dinv[dst]).
__global__ void __launch_bounds__(256) agg_xh_kernel() {
    int node = (blockIdx.x * 256 + threadIdx.x) >> 5;
    if (node >= NN) return;
    int lane = threadIdx.x & 31;
    int slot = lane >> 3;
    int q = lane & 7;
    int beg = g_off[node];
    int deg = g_off[node + 1] - beg;
    float dv = g_deg[node];            // dinv[node]

    float ax0 = 0.f, ax1 = 0.f, ax2 = 0.f, ax3 = 0.f;
    float ah0 = 0.f, ah1 = 0.f, ah2 = 0.f, ah3 = 0.f;
    int j = slot;
    for (; j + 4 < deg; j += 8) {
        ULL r0 = g_edges[beg + j];
        ULL r1 = g_edges[beg + j + 4];
        int s0 = (int)(unsigned)r0, s1 = (int)(unsigned)r1;
        float w0 = __uint_as_float((unsigned)(r0 >> 32));
        float w1 = __uint_as_float((unsigned)(r1 >> 32));
        uint4 p0 = *(const uint4*)(g_xh16 + (size_t)s0 * 64 + q * 8);
        uint4 p1 = *(const uint4*)(g_xh16 + (size_t)s1 * 64 + q * 8);
        {
            float2 a = __half22float2(*(__half2*)&p0.x);
            float2 b = __half22float2(*(__half2*)&p0.y);
            float2 c = __half22float2(*(__half2*)&p0.z);
            float2 d = __half22float2(*(__half2*)&p0.w);
            ax0 = fmaf(w0, a.x, ax0); ax1 = fmaf(w0, a.y, ax1);
            ax2 = fmaf(w0, b.x, ax2); ax3 = fmaf(w0, b.y, ax3);
            ah0 = fmaf(w0, c.x, ah0); ah1 = fmaf(w0, c.y, ah1);
            ah2 = fmaf(w0, d.x, ah2); ah3 = fmaf(w0, d.y, ah3);
        }
        {
            float2 a = __half22float2(*(__half2*)&p1.x);
            float2 b = __half22float2(*(__half2*)&p1.y);
            float2 c = __half22float2(*(__half2*)&p1.z);
            float2 d = __half22float2(*(__half2*)&p1.w);
            ax0 = fmaf(w1, a.x, ax0); ax1 = fmaf(w1, a.y, ax1);
            ax2 = fmaf(w1, b.x, ax2); ax3 = fmaf(w1, b.y, ax3);
            ah0 = fmaf(w1, c.x, ah0); ah1 = fmaf(w1, c.y, ah1);
            ah2 = fmaf(w1, d.x, ah2); ah3 = fmaf(w1, d.y, ah3);
        }
    }
    if (j < deg) {
        ULL r0 = g_edges[beg + j];
        int s0 = (int)(unsigned)r0;
        float w0 = __uint_as_float((unsigned)(r0 >> 32));
        uint4 p0 = *(const uint4*)(g_xh16 + (size_t)s0 * 64 + q * 8);
        float2 a = __half22float2(*(__half2*)&p0.x);
        float2 b = __half22float2(*(__half2*)&p0.y);
        float2 c = __half22float2(*(__half2*)&p0.z);
        float2 d = __half22float2(*(__half2*)&p0.w);
        ax0 = fmaf(w0, a.x, ax0); ax1 = fmaf(w0, a.y, ax1);
        ax2 = fmaf(w0, b.x, ax2); ax3 = fmaf(w0, b.y, ax3);
        ah0 = fmaf(w0, c.x, ah0); ah1 = fmaf(w0, c.y, ah1);
        ah2 = fmaf(w0, d.x, ah2); ah3 = fmaf(w0, d.y, ah3);
    }
#pragma unroll
    for (int off = 8; off <= 16; off <<= 1) {
        ax0 += __shfl_xor_sync(0xffffffffu, ax0, off);
        ax1 += __shfl_xor_sync(0xffffffffu, ax1, off);
        ax2 += __shfl_xor_sync(0xffffffffu, ax2, off);
        ax3 += __shfl_xor_sync(0xffffffffu, ax3, off);
        ah0 += __shfl_xor_sync(0xffffffffu, ah0, off);
        ah1 += __shfl_xor_sync(0xffffffffu, ah1, off);
        ah2 += __shfl_xor_sync(0xffffffffu, ah2, off);
        ah3 += __shfl_xor_sync(0xffffffffu, ah3, off);
    }
    if (slot == 0) {
        *(float4*)(g_aggx + (size_t)node * FH + q * 4) =
            make_float4(dv * ax0, dv * ax1, dv * ax2, dv * ax3);
        *(float4*)(g_aggh + (size_t)node * FH + q * 4) =
            make_float4(dv * ah0, dv * ah1, dv * ah2, dv * ah3);
    }
}

// Gather-aggregate H*R per dst node (fp16 source), same final dinv scale.
__global__ void __launch_bounds__(256) agg_hr_kernel() {
    int node = (blockIdx.x * 256 + threadIdx.x) >> 5;
    if (node >= NN) return;
    int lane = threadIdx.x & 31;
    int slot = lane >> 3;
    int q = lane & 7;
    int beg = g_off[node];
    int deg = g_off[node + 1] - beg;
    float dv = g_deg[node];

    float a0 = 0.f, a1 = 0.f, a2 = 0.f, a3 = 0.f;
    int j = slot;
    for (; j + 4 < deg; j += 8) {
        ULL r0 = g_edges[beg + j];
        ULL r1 = g_edges[beg + j + 4];
        int s0 = (int)(unsigned)r0, s1 = (int)(unsigned)r1;
        float w0 = __uint_as_float((unsigned)(r0 >> 32));
        float w1 = __uint_as_float((unsigned)(r1 >> 32));
        uint2 p0 = *(const uint2*)(g_hr16 + (size_t)s0 * FH + q * 4);
        uint2 p1 = *(const uint2*)(g_hr16 + (size_t)s1 * FH + q * 4);
        {
            float2 a = __half22float2(*(__half2*)&p0.x);
            float2 b = __half22float2(*(__half2*)&p0.y);
            a0 = fmaf(w0, a.x, a0); a1 = fmaf(w0, a.y, a1);
            a2 = fmaf(w0, b.x, a2); a3 = fmaf(w0, b.y, a3);
        }
        {
            float2 a = __half22float2(*(__half2*)&p1.x);
            float2 b = __half22float2(*(__half2*)&p1.y);
            a0 = fmaf(w1, a.x, a0); a1 = fmaf(w1, a.y, a1);
            a2 = fmaf(w1, b.x, a2); a3 = fmaf(w1, b.y, a3);
        }
    }
    if (j < deg) {
        ULL r0 = g_edges[beg + j];
        int s0 = (int)(unsigned)r0;
        float w0 = __uint_as_float((unsigned)(r0 >> 32));
        uint2 p0 = *(const uint2*)(g_hr16 + (size_t)s0 * FH + q * 4);
        float2 a = __half22float2(*(__half2*)&p0.x);
        float2 b = __half22float2(*(__half2*)&p0.y);
        a0 = fmaf(w0, a.x, a0); a1 = fmaf(w0, a.y, a1);
        a2 = fmaf(w0, b.x, a2); a3 = fmaf(w0, b.y, a3);
    }
#pragma unroll
    for (int off = 8; off <= 16; off <<= 1) {
        a0 += __shfl_xor_sync(0xffffffffu, a0, off);
        a1 += __shfl_xor_sync(0xffffffffu, a1, off);
        a2 += __shfl_xor_sync(0xffffffffu, a2, off);
        a3 += __shfl_xor_sync(0xffffffffu, a3, off);
    }
    if (slot == 0)
        *(float4*)(g_agghr + (size_t)node * FH + q * 4) =
            make_float4(dv * a0, dv * a1, dv * a2, dv * a3);
}

// ---------------- gate GEMM: 8 nodes per warp, f32x2 ----------------
// dyn smem floats: sW[8192] | sInF[32*260] | sbz[32] | sbr[32]
#define GATE_SMEM_FLOATS (8192 + 32 * 260 + 64)
__global__ void __launch_bounds__(256) gate_kernel(
    const float* __restrict__ x, const float* __restrict__ H,
    const float* __restrict__ Wxz, const float* __restrict__ bxz,
    const float* __restrict__ Whz, const float* __restrict__ bhz,
    const float* __restrict__ Wxr, const float* __restrict__ bxr,
    const float* __restrict__ Whr, const float* __restrict__ bhr) {
    extern __shared__ __align__(16) float dyn[];
    float* sW   = dyn;                 // [Wxz0,-Wxz1, Whz0,-Whz1, Wxr0,-Wxr1, Whr0,-Whr1]
    float* sInF = dyn + 8192;          // [k][array(4)*64 + node(64)], row = 260 floats
    float* sbz  = dyn + 8192 + 32 * 260;
    float* sbr  = sbz + 32;

    const float* mats[4] = {Wxz, Whz, Wxr, Whr};
    for (int i = threadIdx.x; i < 8 * 1024; i += blockDim.x) {
        int m = i >> 10;
        int r = i & 1023;
        float v = mats[m >> 1][(m & 1) * 1024 + r];
        sW[i] = (m & 1) ? -v : v;
    }
    if (threadIdx.x < 32) {
        sbz[threadIdx.x] = bxz[threadIdx.x] + bhz[threadIdx.x];
        sbr[threadIdx.x] = bxr[threadIdx.x] + bhr[threadIdx.x];
    }
    __syncthreads();

    int w = threadIdx.x >> 5;
    int lane = threadIdx.x & 31;
    int nbase = blockIdx.x * 64 + w * 8;

#pragma unroll
    for (int i = 0; i < 8; i++) {
        int cn = min(nbase + i, NN - 1);
        size_t b = (size_t)cn * FH + lane;
        int off = lane * 260 + w * 8 + i;
        sInF[off]       = x[b];
        sInF[off + 64]  = g_aggx[b];
        sInF[off + 128] = H[b];
        sInF[off + 192] = g_aggh[b];
    }
    __syncwarp();

    ULL az[4], ar[4];
    ULL bz0 = dup2(sbz[lane]), br0 = dup2(sbr[lane]);
#pragma unroll
    for (int j = 0; j < 4; j++) { az[j] = bz0; ar[j] = br0; }
    int pb = w * 4;

#pragma unroll
    for (int k = 0; k < 32; k++) {
        const float* wrow = sW + k * 32 + lane;
        ULL w0 = dup2(wrow[0]);
        ULL w1 = dup2(wrow[1024]);
        ULL w2 = dup2(wrow[2048]);
        ULL w3 = dup2(wrow[3072]);
        ULL w4 = dup2(wrow[4096]);
        ULL w5 = dup2(wrow[5120]);
        ULL w6 = dup2(wrow[6144]);
        ULL w7 = dup2(wrow[7168]);
        const ULL* inrow = (const ULL*)(sInF + k * 260);
#pragma unroll
        for (int j = 0; j < 4; j++) {
            ULL xv = inrow[pb + j];
            ULL av = inrow[32 + pb + j];
            ULL hv = inrow[64 + pb + j];
            ULL gv = inrow[96 + pb + j];
            az[j] = fma2(xv, w0, az[j]); az[j] = fma2(av, w1, az[j]);
            az[j] = fma2(hv, w2, az[j]); az[j] = fma2(gv, w3, az[j]);
            ar[j] = fma2(xv, w4, ar[j]); ar[j] = fma2(av, w5, ar[j]);
            ar[j] = fma2(hv, w6, ar[j]); ar[j] = fma2(gv, w7, ar[j]);
        }
    }

#pragma unroll
    for (int i = 0; i < 8; i++) {
        int node = nbase + i;
        if (node >= NN) break;
        int j = i >> 1;
        float zp = (i & 1) ? hi2(az[j]) : lo2(az[j]);
        float rp = (i & 1) ? hi2(ar[j]) : lo2(ar[j]);
        size_t b = (size_t)node * FH + lane;
        float z = 1.f / (1.f + __expf(-zp));
        float r = 1.f / (1.f + __expf(-rp));
        float hv = sInF[lane * 260 + 128 + w * 8 + i];
        float hr = hv * r;
        g_Z[b]    = z;
        g_hr16[b] = __float2half_rn(hr);   // single HR representation (fp16)
    }
}

// ---------------- out GEMM: 8 nodes per warp, f32x2 ----------------
// dyn smem floats: sW[4096] | sInF[32*260] | sbh[32] | slw[128] | slb[4]
#define OUT_SMEM_FLOATS (4096 + 32 * 260 + 32 + 128 + 4)
__global__ void __launch_bounds__(256) out_kernel(
    const float* __restrict__ x, const float* __restrict__ H,
    const float* __restrict__ Wxh, const float* __restrict__ bxh,
    const float* __restrict__ Whh, const float* __restrict__ bhh,
    const float* __restrict__ lw, const float* __restrict__ lb,
    float* __restrict__ out, int out_size) {
    extern __shared__ __align__(16) float dyn[];
    float* sW   = dyn;                 // [Wxh0, -Wxh1, Whh0, -Whh1]
    float* sInF = dyn + 4096;
    float* sbh  = dyn + 4096 + 32 * 260;
    float* slw  = sbh + 32;
    float* slb  = slw + 128;

    // deferred cleanup for next call (g_deg no longer needed; scan flags)
    int gi = blockIdx.x * 256 + threadIdx.x;
    if (gi < NN) g_deg[gi] = 0.f;
    if (gi < SCAN_BLOCKS) g_scanflag[gi] = 0;

    for (int i = threadIdx.x; i < 4 * 1024; i += blockDim.x) {
        int m = i >> 10;
        int r = i & 1023;
        const float* Wp = (m < 2) ? Wxh : Whh;
        float v = Wp[(m & 1) * 1024 + r];
        sW[i] = (m & 1) ? -v : v;
    }
    if (threadIdx.x < 32) sbh[threadIdx.x] = bxh[threadIdx.x] + bhh[threadIdx.x];
    if (threadIdx.x < 128) slw[threadIdx.x] = lw[threadIdx.x];
    if (threadIdx.x < 4) slb[threadIdx.x] = lb[threadIdx.x];
    __syncthreads();

    int w = threadIdx.x >> 5;
    int lane = threadIdx.x & 31;
    int nbase = blockIdx.x * 64 + w * 8;

#pragma unroll
    for (int i = 0; i < 8; i++) {
        int cn = min(nbase + i, NN - 1);
        size_t b = (size_t)cn * FH + lane;
        int off = lane * 260 + w * 8 + i;
        sInF[off]       = x[b];
        sInF[off + 64]  = g_aggx[b];
        sInF[off + 128] = __half2float(g_hr16[b]);   // HR from fp16
        sInF[off + 192] = g_agghr[b];
    }
    __syncwarp();

    ULL acc[4];
    ULL b0 = dup2(sbh[lane]);
#pragma unroll
    for (int j = 0; j < 4; j++) acc[j] = b0;
    int pb = w * 4;

#pragma unroll
    for (int k = 0; k < 32; k++) {
        const float* wrow = sW + k * 32 + lane;
        ULL w0 = dup2(wrow[0]);
        ULL w1 = dup2(wrow[1024]);
        ULL w2 = dup2(wrow[2048]);
        ULL w3 = dup2(wrow[3072]);
        const ULL* inrow = (const ULL*)(sInF + k * 260);
#pragma unroll
        for (int j = 0; j < 4; j++) {
            ULL xv = inrow[pb + j];
            ULL av = inrow[32 + pb + j];
            ULL hv = inrow[64 + pb + j];
            ULL gv = inrow[96 + pb + j];
            acc[j] = fma2(xv, w0, acc[j]); acc[j] = fma2(av, w1, acc[j]);
            acc[j] = fma2(hv, w2, acc[j]); acc[j] = fma2(gv, w3, acc[j]);
        }
    }

#pragma unroll
    for (int i = 0; i < 8; i++) {
        int node = nbase + i;
        if (node >= NN) break;
        int j = i >> 1;
        float ap = (i & 1) ? hi2(acc[j]) : lo2(acc[j]);
        size_t b = (size_t)node * FH + lane;
        float ht = tanhf(ap);
        float z = g_Z[b];
        float hval = z * H[b] + (1.f - z) * ht;

        long long hidx = (long long)NN * 4 + (long long)b;
        if (hidx < (long long)out_size) out[hidx] = hval;

        float rh = fmaxf(hval, 0.f);
#pragma unroll
        for (int jj = 0; jj < 4; jj++) {
            float s = rh * slw[lane * 4 + jj];
#pragma unroll
            for (int off = 16; off; off >>= 1) s += __shfl_xor_sync(0xffffffffu, s, off);
            if (lane == 0 && (long long)node * 4 + jj < (long long)out_size)
                out[(size_t)node * 4 + jj] = s + slb[jj];
        }
    }
}

// ---------------- launch ----------------
extern "C" void kernel_launch(void* const* d_in, const int* in_sizes, int n_in,
                              void* d_out, int out_size) {
    const float* x   = (const float*)d_in[0];
    const void*  ei  = d_in[1];
    const float* ew  = (const float*)d_in[2];
    const float* H   = (const float*)d_in[3];
    const float* Wxz = (const float*)d_in[4];
    const float* bxz = (const float*)d_in[5];
    const float* Whz = (const float*)d_in[6];
    const float* bhz = (const float*)d_in[7];
    const float* Wxr = (const float*)d_in[8];
    const float* bxr = (const float*)d_in[9];
    const float* Whr = (const float*)d_in[10];
    const float* bhr = (const float*)d_in[11];
    const float* Wxh = (const float*)d_in[12];
    const float* bxh = (const float*)d_in[13];
    const float* Whh = (const float*)d_in[14];
    const float* bhh = (const float*)d_in[15];
    const float* lw  = (const float*)d_in[16];
    const float* lb  = (const float*)d_in[17];
    float* out = (float*)d_out;

    static int smem_set = 0;
    if (!smem_set) {
        cudaFuncSetAttribute(gate_kernel, cudaFuncAttributeMaxDynamicSharedMemorySize,
                             GATE_SMEM_FLOATS * 4);
        cudaFuncSetAttribute(out_kernel, cudaFuncAttributeMaxDynamicSharedMemorySize,
                             OUT_SMEM_FLOATS * 4);
        smem_set = 1;
    }

    packA_kernel<<<(EE + 255) / 256, 256>>>(ei, x, H, ew);
    scan_kernel<<<SCAN_BLOCKS, 1024>>>();
    passB_kernel<<<(EE + 255) / 256, 256>>>(ew);
    agg_xh_kernel<<<(NN + 7) / 8, 256>>>();
    gate_kernel<<<(NN + 63) / 64, 256, GATE_SMEM_FLOATS * 4>>>(
        x, H, Wxz, bxz, Whz, bhz, Wxr, bxr, Whr, bhr);
    agg_hr_kernel<<<(NN + 7) / 8, 256>>>();
    out_kernel<<<(NN + 63) / 64, 256, OUT_SMEM_FLOATS * 4>>>(
        x, H, Wxh, bxh, Whh, bhh, lw, lb, out, out_size);
}